// round 15
// baseline (speedup 1.0000x reference)
#include <cuda_runtime.h>
#include <cuda_fp16.h>
#include <math.h>
#include <stdint.h>

// Problem constants
#define NB   4
#define CI   64
#define CC   256
#define GG   8
#define CG   32
#define KK   9
#define HH   48
#define WW   48
#define HW   (HH*WW)   // 2304
#define HD   40
#define WD   40
#define DD   (HD*WD)   // 1600
#define C2   (2*CC)
#define CPG  64        // 2C/G
#define STRIDE_GATE (NB*CC*HW)
#define LOG2E 1.44269504f

typedef unsigned long long u64;

// Scratch (static device globals; allocation-free rule)
__device__ __half   g_xh16[NB*GG*HW*CPG];              // fp16 [n][g][pos][ci]
__device__ __half   g_in16[NB*HW*320];                 // fp16 [n][pos][64 inp | 256 h]
__device__ uint32_t g_wfrag[7*GG*81*16*32*2];          // conv B frags
__device__ uint32_t g_pwfrag[4*5*4*8*32*2];            // proj B frags
__device__ __half   g_q16 [NB*GG*HW*CG];               // q*tau*log2e fp16 [n][g][pos][32]
__device__ __half   g_k16 [NB*GG*DD*CG];               // k fp16 [n][g][key][32]
__device__ __half   g_v16 [NB*GG*CG*DD];               // v fp16 [n][g][ch][key]
__device__ float    g_a   [NB*CC*HW];
__device__ __half   g_gate16[4*STRIDE_GATE];           // gate pre-acts, fp16 planar

// ---------------------------------------------------------------------------
// mma.sync helpers (compute_103-legal)
// ---------------------------------------------------------------------------
__device__ __forceinline__ uint32_t smem_u32(const void* p) {
    uint32_t a;
    asm("{ .reg .u64 t; cvta.to.shared.u64 t, %1; cvt.u32.u64 %0, t; }"
        : "=r"(a) : "l"(p));
    return a;
}

__device__ __forceinline__ void ldmatrix_x4(uint32_t& r0, uint32_t& r1,
                                            uint32_t& r2, uint32_t& r3,
                                            uint32_t addr) {
    asm volatile("ldmatrix.sync.aligned.m8n8.x4.shared.b16 {%0,%1,%2,%3}, [%4];"
                 : "=r"(r0), "=r"(r1), "=r"(r2), "=r"(r3) : "r"(addr));
}

__device__ __forceinline__ void mma16816(float* c, uint32_t a0, uint32_t a1,
                                         uint32_t a2, uint32_t a3,
                                         uint32_t b0, uint32_t b1) {
    asm volatile("mma.sync.aligned.m16n8k16.row.col.f32.f16.f16.f32 "
                 "{%0,%1,%2,%3}, {%4,%5,%6,%7}, {%8,%9}, {%0,%1,%2,%3};"
                 : "+f"(c[0]), "+f"(c[1]), "+f"(c[2]), "+f"(c[3])
                 : "r"(a0), "r"(a1), "r"(a2), "r"(a3), "r"(b0), "r"(b1));
}

__device__ __forceinline__ uint32_t pack_h2(float a, float b) {
    __half2 h = __floats2half2_rn(a, b);
    return *reinterpret_cast<uint32_t*>(&h);
}

// ---------------------------------------------------------------------------
// Conv weight prep (unchanged)
// ---------------------------------------------------------------------------
#define PREP_SMEM (8*64*81*2)   // 82944 bytes

__global__ __launch_bounds__(256) void prep_wfrag(
    const float* __restrict__ Wq, const float* __restrict__ Wi,
    const float* __restrict__ Wf, const float* __restrict__ Wg2,
    const float* __restrict__ Wo, const float* __restrict__ Wk,
    const float* __restrict__ Wv)
{
    extern __shared__ __half s_w[];
    const int tid = threadIdx.x;
    const int conv = blockIdx.x >> 5;
    const int g    = (blockIdx.x >> 2) & 7;
    const int ob   = blockIdx.x & 3;

    const float* W = (conv == 0) ? Wq : (conv == 1) ? Wi : (conv == 2) ? Wf :
                     (conv == 3) ? Wg2 : (conv == 4) ? Wo : (conv == 5) ? Wk : Wv;
    const float4* src = reinterpret_cast<const float4*>(
        W + (size_t)(g*32 + ob*8)*5184);

    for (int i = tid; i < 10368; i += 256) {
        float4 v = __ldg(src + i);
        int o = i*4;
        s_w[o]   = __float2half(v.x);
        s_w[o+1] = __float2half(v.y);
        s_w[o+2] = __float2half(v.z);
        s_w[o+3] = __float2half(v.w);
    }
    __syncthreads();

    uint32_t* obase = g_wfrag + (size_t)((conv*8 + g)*81)*1024;
    for (int j = tid; j < 81*4*32; j += 256) {
        int t    = j >> 7;
        int r    = j & 127;
        int ks   = r >> 5;
        int lane = r & 31;
        int oc   = lane >> 2;
        int ci0  = ks*16 + (lane & 3)*2;
        __half2 h0, h1;
        h0.x = s_w[(oc*64 + ci0    )*81 + t];
        h0.y = s_w[(oc*64 + ci0 + 1)*81 + t];
        h1.x = s_w[(oc*64 + ci0 + 8)*81 + t];
        h1.y = s_w[(oc*64 + ci0 + 9)*81 + t];
        uint32_t* op = obase + ((size_t)(t*16 + ks*4 + ob)*32 + lane)*2;
        op[0] = *reinterpret_cast<uint32_t*>(&h0);
        op[1] = *reinterpret_cast<uint32_t*>(&h1);
    }
}

// ---------------------------------------------------------------------------
// Proj weight prep (unchanged)
// ---------------------------------------------------------------------------
__global__ __launch_bounds__(256) void prep_pfrag(
    const float* __restrict__ Wx, const float* __restrict__ Wxg)
{
    int j = blockIdx.x * 256 + threadIdx.x;     // total 20480
    if (j >= 20480) return;
    int t = j;
    int lane = t & 31; t >>= 5;
    int nt = t & 7;    t >>= 3;
    int ks = t & 3;    t >>= 2;
    int chunk = t % 5; t /= 5;
    int ob = t;
    if (ob >= 4) return;

    int oc = ob*64 + nt*8 + (lane >> 2);
    int k0 = chunk*64 + ks*16 + (lane & 3)*2;

    auto w = [&](int k) -> float {
        return (k < 64) ? Wx[(size_t)oc*64 + k] : Wxg[(size_t)oc*256 + (k - 64)];
    };
    __half2 h0 = __floats2half2_rn(w(k0),     w(k0 + 1));
    __half2 h1 = __floats2half2_rn(w(k0 + 8), w(k0 + 9));
    uint32_t* op = g_pwfrag + (size_t)j*2;
    op[0] = *reinterpret_cast<uint32_t*>(&h0);
    op[1] = *reinterpret_cast<uint32_t*>(&h1);
}

// ---------------------------------------------------------------------------
// trans16 (unchanged)
// ---------------------------------------------------------------------------
__global__ __launch_bounds__(256) void trans16(
    const float* __restrict__ inp, const float* __restrict__ h)
{
    __shared__ float s[32][33];
    const int pb = blockIdx.x, cb = blockIdx.y, n = blockIdx.z;
    const int t = threadIdx.x;

    for (int i = t; i < 1024; i += 256) {
        int ch = i >> 5, p = i & 31;
        float val;
        if (cb < 2) {
            val = inp[((size_t)n*CI + cb*32 + ch)*HW + pb*32 + p];
        } else {
            val = h[((size_t)n*CC + (cb-2)*32 + ch)*HW + pb*32 + p];
        }
        s[ch][p] = val;
    }
    __syncthreads();

    for (int i = t; i < 1024; i += 256) {
        int p2 = i >> 5, c2 = i & 31;
        __half hv = __float2half(s[c2][p2]);
        g_in16[((size_t)n*HW + pb*32 + p2)*320 + cb*32 + c2] = hv;
        if (cb >= 2) {
            int g = cb - 2;
            g_xh16[(((size_t)(n*GG + g))*HW + pb*32 + p2)*64 + 32 + c2] = hv;
        }
    }
}

// ---------------------------------------------------------------------------
// proj_mma (unchanged)
// ---------------------------------------------------------------------------
__global__ __launch_bounds__(256) void proj_mma()
{
    __shared__ __align__(16) char s_A[128*144];
    __shared__ __align__(16) uint32_t s_B[2048];
    const int tid = threadIdx.x, wid = tid >> 5, lane = tid & 31;
    const int mt = blockIdx.x, ob = blockIdx.y;
    const size_t m_base = (size_t)mt * 128;

    float acc[8][4];
    #pragma unroll
    for (int nt = 0; nt < 8; nt++)
        #pragma unroll
        for (int r = 0; r < 4; r++) acc[nt][r] = 0.f;

    const int lrow = (lane & 7) + ((lane >> 3) & 1)*8;
    const int lkb  = ((lane >> 4) & 1)*16;
    const uint32_t sA = smem_u32(s_A);

    for (int chunk = 0; chunk < 5; chunk++) {
        __syncthreads();
        for (int i = tid; i < 1024; i += 256) {
            int pos = i >> 3, sub = i & 7;
            *reinterpret_cast<uint4*>(s_A + pos*144 + sub*16) =
                *reinterpret_cast<const uint4*>(
                    g_in16 + (m_base + pos)*320 + chunk*64 + sub*8);
        }
        {
            const uint4* bs = reinterpret_cast<const uint4*>(
                g_pwfrag + (size_t)(ob*5 + chunk)*2048);
            uint4* bd = reinterpret_cast<uint4*>(s_B);
            bd[tid]       = bs[tid];
            bd[tid + 256] = bs[tid + 256];
        }
        __syncthreads();

        #pragma unroll
        for (int ks = 0; ks < 4; ks++) {
            uint32_t a0, a1, a2, a3;
            ldmatrix_x4(a0, a1, a2, a3,
                        sA + (uint32_t)(wid*16 + lrow)*144 + (uint32_t)(ks*32 + lkb));
            #pragma unroll
            for (int nt = 0; nt < 8; nt++) {
                u64 v = *reinterpret_cast<const u64*>(s_B + ((ks*8 + nt)*32 + lane)*2);
                mma16816(acc[nt], a0, a1, a2, a3, (uint32_t)v, (uint32_t)(v >> 32));
            }
        }
    }

    const int r  = lane >> 2;
    const int cp = (lane & 3)*2;
    #pragma unroll
    for (int half = 0; half < 2; half++) {
        size_t m = m_base + wid*16 + r + half*8;
        int n = (int)(m / HW), pos = (int)(m % HW);
        #pragma unroll
        for (int nt = 0; nt < 8; nt++) {
            int oc = ob*64 + nt*8 + cp;
            int g = oc >> 5, cg = oc & 31;
            __half2 hv = __floats2half2_rn(acc[nt][half*2], acc[nt][half*2+1]);
            *reinterpret_cast<__half2*>(
                g_xh16 + (((size_t)(n*GG + g))*HW + pos)*64 + cg) = hv;
        }
    }
}

// ---------------------------------------------------------------------------
// Implicit-GEMM grouped 9x9 conv, N-merged v2.
// Output tile 8 rows x 24 cols; input tile 17 rows x 32 cols (528 slots incl.
// ldmatrix overrun pad). M=256 = 16 slabs, 2/warp -> dual-conv acc = 64 regs.
// Per warp-tap: 8 ldmatrix.x4 : 64 mma (dual). B ring: 4 taps x NCONV*4KB,
// register prefetch 2 taps ahead, one sync per 2 taps.
// Modes: 1 = fp16 [pos][32]*scale; 2 = fp16 [pos][32]; 3 = fp16 planar.
// ---------------------------------------------------------------------------
#define TS3      528
#define SMB3     (TS3*144)                 // 76032
#define SMT_CONV (SMB3 + 4*2*4096)         // 108800 bytes

template<int OUTH, int OUTW, int PAD, int NCONV, int M0, int M1>
__device__ __forceinline__ void conv_body2(
    const __half* __restrict__ xin,
    const uint32_t* __restrict__ bf0,
    const uint32_t* __restrict__ bf1,
    void* __restrict__ out0,
    void* __restrict__ out1,
    int y0, int x0, float scale)
{
    extern __shared__ char smem[];
    const uint32_t s_tile = smem_u32(smem);
    const int tid = threadIdx.x, wid = tid >> 5, lane = tid & 31;
    constexpr int NT = 4*NCONV;
    constexpr int RING = NCONV*4096;

    // Input tile: rows 0..16 x 32 cols (+ pad slots), zero-guarded
    for (int i = tid; i < TS3*8; i += 256) {
        int pos = i >> 3, sub = i & 7;
        int rr = pos >> 5, cc = pos & 31;
        int gy = y0 + rr - PAD, gx = x0 + cc - PAD;
        uint4 v = make_uint4(0u, 0u, 0u, 0u);
        if (gy >= 0 && gy < HH && gx >= 0 && gx < WW)
            v = *reinterpret_cast<const uint4*>(xin + ((size_t)(gy*WW + gx) << 6) + (sub << 3));
        *reinterpret_cast<uint4*>(smem + pos*144 + sub*16) = v;
    }
    // Stage taps 0,1
    {
        *reinterpret_cast<uint4*>(smem + SMB3 + tid*16) =
            __ldg(reinterpret_cast<const uint4*>(bf0) + tid);
        *reinterpret_cast<uint4*>(smem + SMB3 + RING + tid*16) =
            __ldg(reinterpret_cast<const uint4*>(bf0 + 1024) + tid);
        if (NCONV == 2) {
            *reinterpret_cast<uint4*>(smem + SMB3 + 4096 + tid*16) =
                __ldg(reinterpret_cast<const uint4*>(bf1) + tid);
            *reinterpret_cast<uint4*>(smem + SMB3 + RING + 4096 + tid*16) =
                __ldg(reinterpret_cast<const uint4*>(bf1 + 1024) + tid);
        }
    }
    __syncthreads();

    float acc[2][NT][4];
    #pragma unroll
    for (int ss = 0; ss < 2; ss++)
        #pragma unroll
        for (int nt = 0; nt < NT; nt++)
            #pragma unroll
            for (int r = 0; r < 4; r++) acc[ss][nt][r] = 0.f;

    const int lrow = (lane & 7) + ((lane >> 3) & 1)*8;
    const int lkb  = ((lane >> 4) & 1)*16;

    auto compute_tap = [&](int t) {
        const uint32_t bb = (uint32_t)(SMB3 + (t & 3)*RING);
        const int tap_off = (t/9)*32 + (t%9);
        #pragma unroll
        for (int ks = 0; ks < 4; ks++) {
            uint32_t b[NT][2];
            #pragma unroll
            for (int nt = 0; nt < NT; nt++) {
                u64 v = *reinterpret_cast<const u64*>(
                    smem + bb + (nt >> 2)*4096 + ((ks*4 + (nt & 3))*32 + lane)*8);
                b[nt][0] = (uint32_t)v;
                b[nt][1] = (uint32_t)(v >> 32);
            }
            #pragma unroll
            for (int ss = 0; ss < 2; ss++) {
                const int pbase = (wid*2 + ss)*16 + tap_off;
                uint32_t a0, a1, a2, a3;
                ldmatrix_x4(a0, a1, a2, a3,
                            s_tile + (uint32_t)(pbase + lrow)*144 + (uint32_t)(ks*32 + lkb));
                #pragma unroll
                for (int nt = 0; nt < NT; nt++)
                    mma16816(acc[ss][nt], a0, a1, a2, a3, b[nt][0], b[nt][1]);
            }
        }
    };

    for (int tt = 0; tt < 81; tt += 2) {
        const bool h2 = (tt + 2 < 81), h3 = (tt + 3 < 81);
        uint4 pA0, pA1, pB0, pB1;
        if (h2) {
            pA0 = __ldg(reinterpret_cast<const uint4*>(bf0 + (tt+2)*1024) + tid);
            if (NCONV == 2)
                pB0 = __ldg(reinterpret_cast<const uint4*>(bf1 + (tt+2)*1024) + tid);
        }
        if (h3) {
            pA1 = __ldg(reinterpret_cast<const uint4*>(bf0 + (tt+3)*1024) + tid);
            if (NCONV == 2)
                pB1 = __ldg(reinterpret_cast<const uint4*>(bf1 + (tt+3)*1024) + tid);
        }

        compute_tap(tt);
        if (tt + 1 < 81) compute_tap(tt + 1);

        if (h2) {
            *reinterpret_cast<uint4*>(smem + SMB3 + ((tt+2) & 3)*RING + tid*16) = pA0;
            if (NCONV == 2)
                *reinterpret_cast<uint4*>(smem + SMB3 + ((tt+2) & 3)*RING + 4096 + tid*16) = pB0;
        }
        if (h3) {
            *reinterpret_cast<uint4*>(smem + SMB3 + ((tt+3) & 3)*RING + tid*16) = pA1;
            if (NCONV == 2)
                *reinterpret_cast<uint4*>(smem + SMB3 + ((tt+3) & 3)*RING + 4096 + tid*16) = pB1;
        }
        __syncthreads();
    }

    const int r  = lane >> 2;
    const int cp = (lane & 3)*2;
    #pragma unroll
    for (int ss = 0; ss < 2; ss++) {
        const int mbase = (wid*2 + ss)*16;
        #pragma unroll
        for (int half = 0; half < 2; half++) {
            int m = mbase + r + half*8;
            int j = m >> 5, x = m & 31;
            if (x < 24) {
                int ox = x0 + x, oy = y0 + j;
                if (ox < OUTW && oy < OUTH) {
                    int off = oy*OUTW + ox;
                    #pragma unroll
                    for (int nt = 0; nt < NT; nt++) {
                        const int MODE = (nt < 4) ? M0 : M1;
                        void* outv = (nt < 4) ? out0 : out1;
                        int oc = (nt & 3)*8 + cp;
                        float v0 = acc[ss][nt][half*2];
                        float v1 = acc[ss][nt][half*2+1];
                        if (MODE == 1 || MODE == 2) {
                            __half* o = (__half*)outv;
                            __half2 h = __floats2half2_rn(v0*scale, v1*scale);
                            *reinterpret_cast<__half2*>(o + (size_t)off*32 + oc) = h;
                        } else {
                            __half* o = (__half*)outv;
                            o[(size_t)oc*OUTH*OUTW + off]     = __float2half(v0);
                            o[(size_t)(oc+1)*OUTH*OUTW + off] = __float2half(v1);
                        }
                    }
                }
            }
        }
    }
}

// ALL 7 convs, N-merged. grid (12, 4, 32):
// y=0: {q,i}; y=1: {f,g}; y=2: {o}; y=3: {k,v} (10 of 12 tiles).
__global__ __launch_bounds__(256, 2) void conv_all_mma(const float* __restrict__ tau)
{
    const int n = blockIdx.z >> 3, g = blockIdx.z & 7;
    const int grp = blockIdx.y;
    const int ty = blockIdx.x >> 1, tx = blockIdx.x & 1;
    const __half* xin = g_xh16 + (size_t)(n*GG + g)*HW*CPG;
    const int y0 = ty*8, x0 = tx*24;

    if (grp == 0) {
        conv_body2<HH, WW, 4, 2, 1, 3>(xin,
            g_wfrag + (size_t)(0*GG + g)*81*1024,
            g_wfrag + (size_t)(1*GG + g)*81*1024,
            g_q16 + (size_t)(n*GG + g)*HW*CG,
            g_gate16 + (size_t)(n*CC + g*CG)*HW,
            y0, x0, tau[g]*LOG2E);
    } else if (grp == 1) {
        conv_body2<HH, WW, 4, 2, 3, 3>(xin,
            g_wfrag + (size_t)(2*GG + g)*81*1024,
            g_wfrag + (size_t)(3*GG + g)*81*1024,
            g_gate16 + (size_t)STRIDE_GATE   + (size_t)(n*CC + g*CG)*HW,
            g_gate16 + (size_t)2*STRIDE_GATE + (size_t)(n*CC + g*CG)*HW,
            y0, x0, 1.f);
    } else if (grp == 2) {
        conv_body2<HH, WW, 4, 1, 3, 3>(xin,
            g_wfrag + (size_t)(4*GG + g)*81*1024,
            g_wfrag + (size_t)(4*GG + g)*81*1024,
            g_gate16 + (size_t)3*STRIDE_GATE + (size_t)(n*CC + g*CG)*HW,
            nullptr, y0, x0, 1.f);
    } else {
        if (ty >= 5) return;
        conv_body2<HD, WD, 0, 2, 2, 3>(xin,
            g_wfrag + (size_t)(5*GG + g)*81*1024,
            g_wfrag + (size_t)(6*GG + g)*81*1024,
            g_k16 + (size_t)(n*GG + g)*DD*CG,
            g_v16 + (size_t)(n*GG + g)*CG*DD,
            y0, x0, 1.f);
    }
}

// ---------------------------------------------------------------------------
// Kernel 3: flash-style mma attention (unchanged)
// ---------------------------------------------------------------------------
__global__ __launch_bounds__(256) void attn_mma()
{
    __shared__ __align__(16) char s_q[128*80];
    __shared__ __align__(16) char s_k[2][64*80];
    __shared__ __align__(16) char s_v[2][32*144];
    const int tid = threadIdx.x, wid = tid >> 5, lane = tid & 31;
    const int n = blockIdx.y >> 3, g = blockIdx.y & 7;
    const int q0 = blockIdx.x * 128;

    const __half* qsrc = g_q16 + (size_t)(n*GG + g)*HW*CG;
    const __half* ksrc = g_k16 + (size_t)(n*GG + g)*DD*CG;
    const __half* vsrc = g_v16 + (size_t)(n*GG + g)*CG*DD;

    for (int i = tid; i < 512; i += 256) {
        int row = i >> 2, sub = i & 3;
        *reinterpret_cast<uint4*>(s_q + row*80 + sub*16) =
            *reinterpret_cast<const uint4*>(
                reinterpret_cast<const char*>(qsrc + (size_t)(q0 + row)*32) + sub*16);
    }
    const int krow = tid >> 2, ksub = tid & 3;
    const int vrow = tid >> 3, vsub = tid & 7;
    {
        uint4 kv = *reinterpret_cast<const uint4*>(
            reinterpret_cast<const char*>(ksrc + (size_t)krow*32) + ksub*16);
        uint4 vv = *reinterpret_cast<const uint4*>(
            reinterpret_cast<const char*>(vsrc + (size_t)vrow*DD) + vsub*16);
        *reinterpret_cast<uint4*>(s_k[0] + krow*80 + ksub*16)  = kv;
        *reinterpret_cast<uint4*>(s_v[0] + vrow*144 + vsub*16) = vv;
    }
    __syncthreads();

    const int m0 = wid*16;
    uint32_t aq[2][4];
    #pragma unroll
    for (int ks = 0; ks < 2; ks++) {
        uint32_t addr = smem_u32(s_q) + (uint32_t)(m0 + (lane & 15))*80
                      + (uint32_t)(ks*32 + (lane >> 4)*16);
        ldmatrix_x4(aq[ks][0], aq[ks][1], aq[ks][2], aq[ks][3], addr);
    }

    float O[4][4];
    #pragma unroll
    for (int nt = 0; nt < 4; nt++)
        #pragma unroll
        for (int r = 0; r < 4; r++) O[nt][r] = 0.f;
    float mrun0 = -1e30f, mrun1 = -1e30f, lsum0 = 0.f, lsum1 = 0.f;

    for (int chn = 0; chn < 25; chn++) {
        const int cur = chn & 1;
        uint4 pk, pv;
        const bool more = (chn < 24);
        if (more) {
            const int d1 = (chn + 1)*64;
            pk = *reinterpret_cast<const uint4*>(
                reinterpret_cast<const char*>(ksrc + (size_t)(d1 + krow)*32) + ksub*16);
            pv = *reinterpret_cast<const uint4*>(
                reinterpret_cast<const char*>(vsrc + (size_t)vrow*DD + d1) + vsub*16);
        }

        const uint32_t sk = smem_u32(s_k[cur]), sv = smem_u32(s_v[cur]);

        float sc[8][4];
        #pragma unroll
        for (int nt = 0; nt < 8; nt++)
            #pragma unroll
            for (int r = 0; r < 4; r++) sc[nt][r] = 0.f;
        #pragma unroll
        for (int ks = 0; ks < 2; ks++) {
            #pragma unroll
            for (int j = 0; j < 4; j++) {
                uint32_t b0, b1, b2, b3;
                uint32_t addr = sk + (uint32_t)(j*16 + (lane & 7) + ((lane >> 4) & 1)*8)*80
                              + (uint32_t)(ks*32 + ((lane >> 3) & 1)*16);
                ldmatrix_x4(b0, b1, b2, b3, addr);
                mma16816(sc[2*j],   aq[ks][0], aq[ks][1], aq[ks][2], aq[ks][3], b0, b1);
                mma16816(sc[2*j+1], aq[ks][0], aq[ks][1], aq[ks][2], aq[ks][3], b2, b3);
            }
        }

        float ml0 = -1e30f, ml1 = -1e30f;
        #pragma unroll
        for (int nt = 0; nt < 8; nt++) {
            ml0 = fmaxf(ml0, fmaxf(sc[nt][0], sc[nt][1]));
            ml1 = fmaxf(ml1, fmaxf(sc[nt][2], sc[nt][3]));
        }
        ml0 = fmaxf(ml0, __shfl_xor_sync(0xffffffffu, ml0, 1));
        ml0 = fmaxf(ml0, __shfl_xor_sync(0xffffffffu, ml0, 2));
        ml1 = fmaxf(ml1, __shfl_xor_sync(0xffffffffu, ml1, 1));
        ml1 = fmaxf(ml1, __shfl_xor_sync(0xffffffffu, ml1, 2));
        float mn0 = fmaxf(mrun0, ml0), mn1 = fmaxf(mrun1, ml1);
        float scl0 = exp2f(mrun0 - mn0), scl1 = exp2f(mrun1 - mn1);
        mrun0 = mn0; mrun1 = mn1;
        lsum0 *= scl0; lsum1 *= scl1;
        #pragma unroll
        for (int nt = 0; nt < 4; nt++) {
            O[nt][0] *= scl0; O[nt][1] *= scl0;
            O[nt][2] *= scl1; O[nt][3] *= scl1;
        }
        #pragma unroll
        for (int nt = 0; nt < 8; nt++) {
            sc[nt][0] = exp2f(sc[nt][0] - mn0);
            sc[nt][1] = exp2f(sc[nt][1] - mn0);
            sc[nt][2] = exp2f(sc[nt][2] - mn1);
            sc[nt][3] = exp2f(sc[nt][3] - mn1);
            lsum0 += sc[nt][0] + sc[nt][1];
            lsum1 += sc[nt][2] + sc[nt][3];
        }

        #pragma unroll
        for (int ks = 0; ks < 4; ks++) {
            uint32_t a0 = pack_h2(sc[2*ks][0],   sc[2*ks][1]);
            uint32_t a1 = pack_h2(sc[2*ks][2],   sc[2*ks][3]);
            uint32_t a2 = pack_h2(sc[2*ks+1][0], sc[2*ks+1][1]);
            uint32_t a3 = pack_h2(sc[2*ks+1][2], sc[2*ks+1][3]);
            #pragma unroll
            for (int j = 0; j < 2; j++) {
                uint32_t b0, b1, b2, b3;
                uint32_t addr = sv + (uint32_t)(j*16 + (lane & 7) + ((lane >> 4) & 1)*8)*144
                              + (uint32_t)(ks*32 + ((lane >> 3) & 1)*16);
                ldmatrix_x4(b0, b1, b2, b3, addr);
                mma16816(O[2*j],   a0, a1, a2, a3, b0, b1);
                mma16816(O[2*j+1], a0, a1, a2, a3, b2, b3);
            }
        }

        if (more) {
            *reinterpret_cast<uint4*>(s_k[1-cur] + krow*80 + ksub*16)  = pk;
            *reinterpret_cast<uint4*>(s_v[1-cur] + vrow*144 + vsub*16) = pv;
        }
        __syncthreads();
    }

    lsum0 += __shfl_xor_sync(0xffffffffu, lsum0, 1);
    lsum0 += __shfl_xor_sync(0xffffffffu, lsum0, 2);
    lsum1 += __shfl_xor_sync(0xffffffffu, lsum1, 1);
    lsum1 += __shfl_xor_sync(0xffffffffu, lsum1, 2);
    float inv0 = 1.f / lsum0, inv1 = 1.f / lsum1;

    const int row0 = q0 + m0 + (lane >> 2);
    const int cp = (lane & 3)*2;
    float* abase = g_a + (size_t)(n*CC + g*CG)*HW;
    #pragma unroll
    for (int nt = 0; nt < 4; nt++) {
        int ch = nt*8 + cp;
        abase[(size_t)ch*HW + row0]           = O[nt][0]*inv0;
        abase[(size_t)(ch+1)*HW + row0]       = O[nt][1]*inv0;
        abase[(size_t)ch*HW + row0 + 8]       = O[nt][2]*inv1;
        abase[(size_t)(ch+1)*HW + row0 + 8]   = O[nt][3]*inv1;
    }
}

// ---------------------------------------------------------------------------
// Kernel 4: LSTM epilogue (unchanged)
// ---------------------------------------------------------------------------
__device__ __forceinline__ float sigmoidf_(float x) { return 1.f / (1.f + __expf(-x)); }

__global__ __launch_bounds__(256) void lstm_kernel(
    const float* __restrict__ Wa0, const float* __restrict__ Wa1,
    const float* __restrict__ Wa2, const float* __restrict__ Wa3,
    const float* __restrict__ b0,  const float* __restrict__ b1,
    const float* __restrict__ b2,  const float* __restrict__ b3,
    const float* __restrict__ c_prev, float* __restrict__ out)
{
    __shared__ float s_a[CC][8];
    const int n  = blockIdx.y;
    const int p0 = blockIdx.x * 8;
    const int t  = threadIdx.x;

    for (int i = t; i < CC*8; i += 256) {
        int ch = i >> 3, p = i & 7;
        s_a[ch][p] = g_a[((size_t)(n*CC + ch))*HW + p0 + p];
    }
    __syncthreads();

    const int c = t, g = c >> 5;
    float a0[8], a1[8], a2[8], a3[8];
    #pragma unroll
    for (int p = 0; p < 8; p++) { a0[p] = a1[p] = a2[p] = a3[p] = 0.f; }

    const float* wa0 = Wa0 + c*CG;
    const float* wa1 = Wa1 + c*CG;
    const float* wa2 = Wa2 + c*CG;
    const float* wa3 = Wa3 + c*CG;
    for (int cg = 0; cg < CG; cg++) {
        float w0 = wa0[cg], w1 = wa1[cg], w2 = wa2[cg], w3 = wa3[cg];
        const float* ar = s_a[g*CG + cg];
        #pragma unroll
        for (int p = 0; p < 8; p++) {
            float av = ar[p];
            a0[p] = fmaf(w0, av, a0[p]);
            a1[p] = fmaf(w1, av, a1[p]);
            a2[p] = fmaf(w2, av, a2[p]);
            a3[p] = fmaf(w3, av, a3[p]);
        }
    }

    const float bi = b0[c], bf = b1[c], bg = b2[c], bo = b3[c];
    const int idx0 = (n*CC + c)*HW + p0;
    #pragma unroll
    for (int p = 0; p < 8; p++) {
        int idx = idx0 + p;
        float gi = sigmoidf_(a0[p] + __half2float(g_gate16[                idx]) + bi);
        float gf = sigmoidf_(a1[p] + __half2float(g_gate16[  STRIDE_GATE + idx]) + bf);
        float gg = tanhf    (a2[p] + __half2float(g_gate16[2*STRIDE_GATE + idx]) + bg);
        float go = sigmoidf_(a3[p] + __half2float(g_gate16[3*STRIDE_GATE + idx]) + bo);
        float cn = gf * c_prev[idx] + gi * gg;
        out[idx] = go * tanhf(cn);
    }
}

// ---------------------------------------------------------------------------
extern "C" void kernel_launch(void* const* d_in, const int* in_sizes, int n_in,
                              void* d_out, int out_size)
{
    const float* inp    = (const float*)d_in[0];
    const float* h_prev = (const float*)d_in[1];
    const float* c_prev = (const float*)d_in[2];
    const float* Wx     = (const float*)d_in[3];
    const float* Wxg    = (const float*)d_in[4];
    const float* tau    = (const float*)d_in[5];
    const float* Wq     = (const float*)d_in[6];
    const float* Wk     = (const float*)d_in[7];
    const float* Wv     = (const float*)d_in[8];
    const float* Wa_i   = (const float*)d_in[9];
    const float* Wxh_i  = (const float*)d_in[10];
    const float* b_i    = (const float*)d_in[11];
    const float* Wa_f   = (const float*)d_in[12];
    const float* Wxh_f  = (const float*)d_in[13];
    const float* b_f    = (const float*)d_in[14];
    const float* Wa_g   = (const float*)d_in[15];
    const float* Wxh_g  = (const float*)d_in[16];
    const float* b_g    = (const float*)d_in[17];
    const float* Wa_o   = (const float*)d_in[18];
    const float* Wxh_o  = (const float*)d_in[19];
    const float* b_o    = (const float*)d_in[20];
    float* out = (float*)d_out;

    cudaFuncSetAttribute(conv_all_mma,
                         cudaFuncAttributeMaxDynamicSharedMemorySize, SMT_CONV);
    cudaFuncSetAttribute(prep_wfrag,
                         cudaFuncAttributeMaxDynamicSharedMemorySize, PREP_SMEM);

    prep_wfrag      <<<224, 256, PREP_SMEM>>>(Wq, Wxh_i, Wxh_f, Wxh_g, Wxh_o, Wk, Wv);
    prep_pfrag      <<<80, 256>>>(Wx, Wxg);
    trans16         <<<dim3(HW/32, 10, NB), 256>>>(inp, h_prev);
    proj_mma        <<<dim3(72, 4), 256>>>();
    conv_all_mma    <<<dim3(12, 4, NB*GG), 256, SMT_CONV>>>(tau);
    attn_mma        <<<dim3(HW/128, NB*GG), 256>>>();
    lstm_kernel     <<<dim3(HW/8, NB), 256>>>(Wa_i, Wa_f, Wa_g, Wa_o,
                                              b_i, b_f, b_g, b_o, c_prev, out);
}

// round 16
// speedup vs baseline: 1.0192x; 1.0192x over previous
#include <cuda_runtime.h>
#include <cuda_fp16.h>
#include <math.h>
#include <stdint.h>

// Problem constants
#define NB   4
#define CI   64
#define CC   256
#define GG   8
#define CG   32
#define KK   9
#define HH   48
#define WW   48
#define HW   (HH*WW)   // 2304
#define HD   40
#define WD   40
#define DD   (HD*WD)   // 1600
#define C2   (2*CC)
#define CPG  64        // 2C/G
#define STRIDE_GATE (NB*CC*HW)
#define LOG2E 1.44269504f

typedef unsigned long long u64;

// Scratch (static device globals; allocation-free rule)
__device__ __half   g_xh16[NB*GG*HW*CPG];              // fp16 [n][g][pos][ci]
__device__ __half   g_in16[NB*HW*320];                 // fp16 [n][pos][64 inp | 256 h]
__device__ uint32_t g_wfrag[7*GG*81*16*32*2];          // conv B frags
__device__ uint32_t g_pwfrag[4*5*4*8*32*2];            // proj B frags
__device__ __half   g_q16 [NB*GG*HW*CG];               // q*tau*log2e fp16 [n][g][pos][32]
__device__ __half   g_k16 [NB*GG*DD*CG];               // k fp16 [n][g][key][32]
__device__ __half   g_v16 [NB*GG*CG*DD];               // v fp16 [n][g][ch][key]
__device__ float    g_a   [NB*CC*HW];
__device__ __half   g_gate16[4*STRIDE_GATE];           // gate pre-acts, fp16 planar

// ---------------------------------------------------------------------------
// mma.sync + fast-math helpers (compute_103-legal)
// ---------------------------------------------------------------------------
__device__ __forceinline__ uint32_t smem_u32(const void* p) {
    uint32_t a;
    asm("{ .reg .u64 t; cvta.to.shared.u64 t, %1; cvt.u32.u64 %0, t; }"
        : "=r"(a) : "l"(p));
    return a;
}

__device__ __forceinline__ void ldmatrix_x4(uint32_t& r0, uint32_t& r1,
                                            uint32_t& r2, uint32_t& r3,
                                            uint32_t addr) {
    asm volatile("ldmatrix.sync.aligned.m8n8.x4.shared.b16 {%0,%1,%2,%3}, [%4];"
                 : "=r"(r0), "=r"(r1), "=r"(r2), "=r"(r3) : "r"(addr));
}

__device__ __forceinline__ void mma16816(float* c, uint32_t a0, uint32_t a1,
                                         uint32_t a2, uint32_t a3,
                                         uint32_t b0, uint32_t b1) {
    asm volatile("mma.sync.aligned.m16n8k16.row.col.f32.f16.f16.f32 "
                 "{%0,%1,%2,%3}, {%4,%5,%6,%7}, {%8,%9}, {%0,%1,%2,%3};"
                 : "+f"(c[0]), "+f"(c[1]), "+f"(c[2]), "+f"(c[3])
                 : "r"(a0), "r"(a1), "r"(a2), "r"(a3), "r"(b0), "r"(b1));
}

__device__ __forceinline__ uint32_t pack_h2(float a, float b) {
    __half2 h = __floats2half2_rn(a, b);
    return *reinterpret_cast<uint32_t*>(&h);
}

__device__ __forceinline__ float ex2f(float x) {
    float y; asm("ex2.approx.f32 %0, %1;" : "=f"(y) : "f"(x)); return y;
}
__device__ __forceinline__ float tanhfast(float x) {
    float y; asm("tanh.approx.f32 %0, %1;" : "=f"(y) : "f"(x)); return y;
}
__device__ __forceinline__ float sigfast(float x) {
    return fmaf(0.5f, tanhfast(0.5f*x), 0.5f);
}

// ---------------------------------------------------------------------------
// Conv weight prep (unchanged)
// ---------------------------------------------------------------------------
#define PREP_SMEM (8*64*81*2)   // 82944 bytes

__global__ __launch_bounds__(256) void prep_wfrag(
    const float* __restrict__ Wq, const float* __restrict__ Wi,
    const float* __restrict__ Wf, const float* __restrict__ Wg2,
    const float* __restrict__ Wo, const float* __restrict__ Wk,
    const float* __restrict__ Wv)
{
    extern __shared__ __half s_w[];
    const int tid = threadIdx.x;
    const int conv = blockIdx.x >> 5;
    const int g    = (blockIdx.x >> 2) & 7;
    const int ob   = blockIdx.x & 3;

    const float* W = (conv == 0) ? Wq : (conv == 1) ? Wi : (conv == 2) ? Wf :
                     (conv == 3) ? Wg2 : (conv == 4) ? Wo : (conv == 5) ? Wk : Wv;
    const float4* src = reinterpret_cast<const float4*>(
        W + (size_t)(g*32 + ob*8)*5184);

    for (int i = tid; i < 10368; i += 256) {
        float4 v = __ldg(src + i);
        int o = i*4;
        s_w[o]   = __float2half(v.x);
        s_w[o+1] = __float2half(v.y);
        s_w[o+2] = __float2half(v.z);
        s_w[o+3] = __float2half(v.w);
    }
    __syncthreads();

    uint32_t* obase = g_wfrag + (size_t)((conv*8 + g)*81)*1024;
    for (int j = tid; j < 81*4*32; j += 256) {
        int t    = j >> 7;
        int r    = j & 127;
        int ks   = r >> 5;
        int lane = r & 31;
        int oc   = lane >> 2;
        int ci0  = ks*16 + (lane & 3)*2;
        __half2 h0, h1;
        h0.x = s_w[(oc*64 + ci0    )*81 + t];
        h0.y = s_w[(oc*64 + ci0 + 1)*81 + t];
        h1.x = s_w[(oc*64 + ci0 + 8)*81 + t];
        h1.y = s_w[(oc*64 + ci0 + 9)*81 + t];
        uint32_t* op = obase + ((size_t)(t*16 + ks*4 + ob)*32 + lane)*2;
        op[0] = *reinterpret_cast<uint32_t*>(&h0);
        op[1] = *reinterpret_cast<uint32_t*>(&h1);
    }
}

// ---------------------------------------------------------------------------
// Proj weight prep (unchanged)
// ---------------------------------------------------------------------------
__global__ __launch_bounds__(256) void prep_pfrag(
    const float* __restrict__ Wx, const float* __restrict__ Wxg)
{
    int j = blockIdx.x * 256 + threadIdx.x;     // total 20480
    if (j >= 20480) return;
    int t = j;
    int lane = t & 31; t >>= 5;
    int nt = t & 7;    t >>= 3;
    int ks = t & 3;    t >>= 2;
    int chunk = t % 5; t /= 5;
    int ob = t;
    if (ob >= 4) return;

    int oc = ob*64 + nt*8 + (lane >> 2);
    int k0 = chunk*64 + ks*16 + (lane & 3)*2;

    auto w = [&](int k) -> float {
        return (k < 64) ? Wx[(size_t)oc*64 + k] : Wxg[(size_t)oc*256 + (k - 64)];
    };
    __half2 h0 = __floats2half2_rn(w(k0),     w(k0 + 1));
    __half2 h1 = __floats2half2_rn(w(k0 + 8), w(k0 + 9));
    uint32_t* op = g_pwfrag + (size_t)j*2;
    op[0] = *reinterpret_cast<uint32_t*>(&h0);
    op[1] = *reinterpret_cast<uint32_t*>(&h1);
}

// ---------------------------------------------------------------------------
// trans16 (unchanged)
// ---------------------------------------------------------------------------
__global__ __launch_bounds__(256) void trans16(
    const float* __restrict__ inp, const float* __restrict__ h)
{
    __shared__ float s[32][33];
    const int pb = blockIdx.x, cb = blockIdx.y, n = blockIdx.z;
    const int t = threadIdx.x;

    for (int i = t; i < 1024; i += 256) {
        int ch = i >> 5, p = i & 31;
        float val;
        if (cb < 2) {
            val = inp[((size_t)n*CI + cb*32 + ch)*HW + pb*32 + p];
        } else {
            val = h[((size_t)n*CC + (cb-2)*32 + ch)*HW + pb*32 + p];
        }
        s[ch][p] = val;
    }
    __syncthreads();

    for (int i = t; i < 1024; i += 256) {
        int p2 = i >> 5, c2 = i & 31;
        __half hv = __float2half(s[c2][p2]);
        g_in16[((size_t)n*HW + pb*32 + p2)*320 + cb*32 + c2] = hv;
        if (cb >= 2) {
            int g = cb - 2;
            g_xh16[(((size_t)(n*GG + g))*HW + pb*32 + p2)*64 + 32 + c2] = hv;
        }
    }
}

// ---------------------------------------------------------------------------
// proj_mma (unchanged)
// ---------------------------------------------------------------------------
__global__ __launch_bounds__(256) void proj_mma()
{
    __shared__ __align__(16) char s_A[128*144];
    __shared__ __align__(16) uint32_t s_B[2048];
    const int tid = threadIdx.x, wid = tid >> 5, lane = tid & 31;
    const int mt = blockIdx.x, ob = blockIdx.y;
    const size_t m_base = (size_t)mt * 128;

    float acc[8][4];
    #pragma unroll
    for (int nt = 0; nt < 8; nt++)
        #pragma unroll
        for (int r = 0; r < 4; r++) acc[nt][r] = 0.f;

    const int lrow = (lane & 7) + ((lane >> 3) & 1)*8;
    const int lkb  = ((lane >> 4) & 1)*16;
    const uint32_t sA = smem_u32(s_A);

    for (int chunk = 0; chunk < 5; chunk++) {
        __syncthreads();
        for (int i = tid; i < 1024; i += 256) {
            int pos = i >> 3, sub = i & 7;
            *reinterpret_cast<uint4*>(s_A + pos*144 + sub*16) =
                *reinterpret_cast<const uint4*>(
                    g_in16 + (m_base + pos)*320 + chunk*64 + sub*8);
        }
        {
            const uint4* bs = reinterpret_cast<const uint4*>(
                g_pwfrag + (size_t)(ob*5 + chunk)*2048);
            uint4* bd = reinterpret_cast<uint4*>(s_B);
            bd[tid]       = bs[tid];
            bd[tid + 256] = bs[tid + 256];
        }
        __syncthreads();

        #pragma unroll
        for (int ks = 0; ks < 4; ks++) {
            uint32_t a0, a1, a2, a3;
            ldmatrix_x4(a0, a1, a2, a3,
                        sA + (uint32_t)(wid*16 + lrow)*144 + (uint32_t)(ks*32 + lkb));
            #pragma unroll
            for (int nt = 0; nt < 8; nt++) {
                u64 v = *reinterpret_cast<const u64*>(s_B + ((ks*8 + nt)*32 + lane)*2);
                mma16816(acc[nt], a0, a1, a2, a3, (uint32_t)v, (uint32_t)(v >> 32));
            }
        }
    }

    const int r  = lane >> 2;
    const int cp = (lane & 3)*2;
    #pragma unroll
    for (int half = 0; half < 2; half++) {
        size_t m = m_base + wid*16 + r + half*8;
        int n = (int)(m / HW), pos = (int)(m % HW);
        #pragma unroll
        for (int nt = 0; nt < 8; nt++) {
            int oc = ob*64 + nt*8 + cp;
            int g = oc >> 5, cg = oc & 31;
            __half2 hv = __floats2half2_rn(acc[nt][half*2], acc[nt][half*2+1]);
            *reinterpret_cast<__half2*>(
                g_xh16 + (((size_t)(n*GG + g))*HW + pos)*64 + cg) = hv;
        }
    }
}

// ---------------------------------------------------------------------------
// Implicit-GEMM grouped 9x9 conv via mma.sync (R12 proven config, reverted).
// Output 12 rows x 24 cols, input tile stride 32 (656 slots).
// ---------------------------------------------------------------------------
#define TS2      656
#define SMB_OFF  (TS2*144)            // 94464
#define SMT_CONV (SMB_OFF + 16384)    // 110848 bytes (4 x 4KB B ring)

template<int OUTH, int OUTW, int PAD, int MODE>
__device__ __forceinline__ void conv_mma_body(
    const __half* __restrict__ xin,
    const uint32_t* __restrict__ bfrag,
    void* __restrict__ outv,
    int y0, int x0, float scale)
{
    extern __shared__ char smem[];
    const uint32_t s_tile = smem_u32(smem);
    const int tid = threadIdx.x, wid = tid >> 5, lane = tid & 31;

    for (int i = tid; i < TS2*8; i += 256) {
        int pos = i >> 3, sub = i & 7;
        int rr = pos >> 5, cc = pos & 31;
        int gy = y0 + rr - PAD, gx = x0 + cc - PAD;
        uint4 v = make_uint4(0u, 0u, 0u, 0u);
        if (gy >= 0 && gy < HH && gx >= 0 && gx < WW)
            v = *reinterpret_cast<const uint4*>(xin + ((size_t)(gy*WW + gx) << 6) + (sub << 3));
        *reinterpret_cast<uint4*>(smem + pos*144 + sub*16) = v;
    }
    {
        uint4 v0 = __ldg(reinterpret_cast<const uint4*>(bfrag) + tid);
        uint4 v1 = __ldg(reinterpret_cast<const uint4*>(bfrag + 1024) + tid);
        *reinterpret_cast<uint4*>(smem + SMB_OFF + tid*16)        = v0;
        *reinterpret_cast<uint4*>(smem + SMB_OFF + 4096 + tid*16) = v1;
    }
    __syncthreads();

    float acc[3][4][4];
    #pragma unroll
    for (int ss = 0; ss < 3; ss++)
        #pragma unroll
        for (int nt = 0; nt < 4; nt++)
            #pragma unroll
            for (int r = 0; r < 4; r++) acc[ss][nt][r] = 0.f;

    const int lrow = (lane & 7) + ((lane >> 3) & 1)*8;
    const int lkb  = ((lane >> 4) & 1)*16;

    auto compute_tap = [&](int t) {
        const uint32_t bb = (uint32_t)(SMB_OFF + (t & 3)*4096);
        const int tap_off = (t/9)*32 + (t%9);
        #pragma unroll
        for (int ks = 0; ks < 4; ks++) {
            uint32_t b[4][2];
            #pragma unroll
            for (int nt = 0; nt < 4; nt++) {
                u64 v = *reinterpret_cast<const u64*>(
                    smem + bb + ((ks*4 + nt)*32 + lane)*8);
                b[nt][0] = (uint32_t)v;
                b[nt][1] = (uint32_t)(v >> 32);
            }
            #pragma unroll
            for (int ss = 0; ss < 3; ss++) {
                const int pbase = (ss*8 + wid)*16 + tap_off;
                uint32_t a0, a1, a2, a3;
                ldmatrix_x4(a0, a1, a2, a3,
                            s_tile + (uint32_t)(pbase + lrow)*144 + (uint32_t)(ks*32 + lkb));
                #pragma unroll
                for (int nt = 0; nt < 4; nt++)
                    mma16816(acc[ss][nt], a0, a1, a2, a3, b[nt][0], b[nt][1]);
            }
        }
    };

    for (int tt = 0; tt < 81; tt += 2) {
        const bool h2 = (tt + 2 < 81), h3 = (tt + 3 < 81);
        uint4 pf0, pf1;
        if (h2) pf0 = __ldg(reinterpret_cast<const uint4*>(bfrag + (tt+2)*1024) + tid);
        if (h3) pf1 = __ldg(reinterpret_cast<const uint4*>(bfrag + (tt+3)*1024) + tid);

        compute_tap(tt);
        if (tt + 1 < 81) compute_tap(tt + 1);

        if (h2) *reinterpret_cast<uint4*>(smem + SMB_OFF + ((tt+2) & 3)*4096 + tid*16) = pf0;
        if (h3) *reinterpret_cast<uint4*>(smem + SMB_OFF + ((tt+3) & 3)*4096 + tid*16) = pf1;
        __syncthreads();
    }

    const int r  = lane >> 2;
    const int cp = (lane & 3)*2;
    #pragma unroll
    for (int ss = 0; ss < 3; ss++) {
        const int mbase = (ss*8 + wid)*16;
        #pragma unroll
        for (int half = 0; half < 2; half++) {
            int m = mbase + r + half*8;
            int j = m >> 5, x = m & 31;
            if (x < 24) {
                int ox = x0 + x, oy = y0 + j;
                if (ox < OUTW && oy < OUTH) {
                    int off = oy*OUTW + ox;
                    #pragma unroll
                    for (int nt = 0; nt < 4; nt++) {
                        int oc = nt*8 + cp;
                        float v0 = acc[ss][nt][half*2];
                        float v1 = acc[ss][nt][half*2+1];
                        if (MODE == 1 || MODE == 2) {
                            __half* o = (__half*)outv;
                            __half2 h = __floats2half2_rn(v0*scale, v1*scale);
                            *reinterpret_cast<__half2*>(o + (size_t)off*32 + oc) = h;
                        } else {
                            __half* o = (__half*)outv;
                            o[(size_t)oc*OUTH*OUTW + off]     = __float2half(v0);
                            o[(size_t)(oc+1)*OUTH*OUTW + off] = __float2half(v1);
                        }
                    }
                }
            }
        }
    }
}

// ALL 7 convs. grid (8, 7, 32): x = tile (4 y-tiles of 12 x 2 x-tiles of 24).
__global__ __launch_bounds__(256) void conv_all_mma(const float* __restrict__ tau)
{
    const int n = blockIdx.z >> 3, g = blockIdx.z & 7;
    const int conv = blockIdx.y;
    const int ty = blockIdx.x >> 1, tx = blockIdx.x & 1;
    const __half* xin = g_xh16 + (size_t)(n*GG + g)*HW*CPG;
    const uint32_t* bf = g_wfrag + (size_t)(conv*GG + g)*81*1024;

    if (conv == 0) {
        conv_mma_body<HH, WW, 4, 1>(xin, bf,
            g_q16 + (size_t)(n*GG + g)*HW*CG, ty*12, tx*24, tau[g]*LOG2E);
    } else if (conv < 5) {
        conv_mma_body<HH, WW, 4, 3>(xin, bf,
            g_gate16 + (size_t)(conv-1)*STRIDE_GATE + (size_t)(n*CC + g*CG)*HW,
            ty*12, tx*24, 1.f);
    } else if (conv == 5) {
        conv_mma_body<HD, WD, 0, 2>(xin, bf,
            g_k16 + (size_t)(n*GG + g)*DD*CG, ty*12, tx*24, 1.f);
    } else {
        conv_mma_body<HD, WD, 0, 3>(xin, bf,
            g_v16 + (size_t)(n*GG + g)*CG*DD, ty*12, tx*24, 1.f);
    }
}

// ---------------------------------------------------------------------------
// Kernel 3: flash-style mma attention (ex2.approx for all exponentials)
// ---------------------------------------------------------------------------
__global__ __launch_bounds__(256) void attn_mma()
{
    __shared__ __align__(16) char s_q[128*80];
    __shared__ __align__(16) char s_k[2][64*80];
    __shared__ __align__(16) char s_v[2][32*144];
    const int tid = threadIdx.x, wid = tid >> 5, lane = tid & 31;
    const int n = blockIdx.y >> 3, g = blockIdx.y & 7;
    const int q0 = blockIdx.x * 128;

    const __half* qsrc = g_q16 + (size_t)(n*GG + g)*HW*CG;
    const __half* ksrc = g_k16 + (size_t)(n*GG + g)*DD*CG;
    const __half* vsrc = g_v16 + (size_t)(n*GG + g)*CG*DD;

    for (int i = tid; i < 512; i += 256) {
        int row = i >> 2, sub = i & 3;
        *reinterpret_cast<uint4*>(s_q + row*80 + sub*16) =
            *reinterpret_cast<const uint4*>(
                reinterpret_cast<const char*>(qsrc + (size_t)(q0 + row)*32) + sub*16);
    }
    const int krow = tid >> 2, ksub = tid & 3;
    const int vrow = tid >> 3, vsub = tid & 7;
    {
        uint4 kv = *reinterpret_cast<const uint4*>(
            reinterpret_cast<const char*>(ksrc + (size_t)krow*32) + ksub*16);
        uint4 vv = *reinterpret_cast<const uint4*>(
            reinterpret_cast<const char*>(vsrc + (size_t)vrow*DD) + vsub*16);
        *reinterpret_cast<uint4*>(s_k[0] + krow*80 + ksub*16)  = kv;
        *reinterpret_cast<uint4*>(s_v[0] + vrow*144 + vsub*16) = vv;
    }
    __syncthreads();

    const int m0 = wid*16;
    uint32_t aq[2][4];
    #pragma unroll
    for (int ks = 0; ks < 2; ks++) {
        uint32_t addr = smem_u32(s_q) + (uint32_t)(m0 + (lane & 15))*80
                      + (uint32_t)(ks*32 + (lane >> 4)*16);
        ldmatrix_x4(aq[ks][0], aq[ks][1], aq[ks][2], aq[ks][3], addr);
    }

    float O[4][4];
    #pragma unroll
    for (int nt = 0; nt < 4; nt++)
        #pragma unroll
        for (int r = 0; r < 4; r++) O[nt][r] = 0.f;
    float mrun0 = -1e30f, mrun1 = -1e30f, lsum0 = 0.f, lsum1 = 0.f;

    for (int chn = 0; chn < 25; chn++) {
        const int cur = chn & 1;
        uint4 pk, pv;
        const bool more = (chn < 24);
        if (more) {
            const int d1 = (chn + 1)*64;
            pk = *reinterpret_cast<const uint4*>(
                reinterpret_cast<const char*>(ksrc + (size_t)(d1 + krow)*32) + ksub*16);
            pv = *reinterpret_cast<const uint4*>(
                reinterpret_cast<const char*>(vsrc + (size_t)vrow*DD + d1) + vsub*16);
        }

        const uint32_t sk = smem_u32(s_k[cur]), sv = smem_u32(s_v[cur]);

        float sc[8][4];
        #pragma unroll
        for (int nt = 0; nt < 8; nt++)
            #pragma unroll
            for (int r = 0; r < 4; r++) sc[nt][r] = 0.f;
        #pragma unroll
        for (int ks = 0; ks < 2; ks++) {
            #pragma unroll
            for (int j = 0; j < 4; j++) {
                uint32_t b0, b1, b2, b3;
                uint32_t addr = sk + (uint32_t)(j*16 + (lane & 7) + ((lane >> 4) & 1)*8)*80
                              + (uint32_t)(ks*32 + ((lane >> 3) & 1)*16);
                ldmatrix_x4(b0, b1, b2, b3, addr);
                mma16816(sc[2*j],   aq[ks][0], aq[ks][1], aq[ks][2], aq[ks][3], b0, b1);
                mma16816(sc[2*j+1], aq[ks][0], aq[ks][1], aq[ks][2], aq[ks][3], b2, b3);
            }
        }

        float ml0 = -1e30f, ml1 = -1e30f;
        #pragma unroll
        for (int nt = 0; nt < 8; nt++) {
            ml0 = fmaxf(ml0, fmaxf(sc[nt][0], sc[nt][1]));
            ml1 = fmaxf(ml1, fmaxf(sc[nt][2], sc[nt][3]));
        }
        ml0 = fmaxf(ml0, __shfl_xor_sync(0xffffffffu, ml0, 1));
        ml0 = fmaxf(ml0, __shfl_xor_sync(0xffffffffu, ml0, 2));
        ml1 = fmaxf(ml1, __shfl_xor_sync(0xffffffffu, ml1, 1));
        ml1 = fmaxf(ml1, __shfl_xor_sync(0xffffffffu, ml1, 2));
        float mn0 = fmaxf(mrun0, ml0), mn1 = fmaxf(mrun1, ml1);
        float scl0 = ex2f(mrun0 - mn0), scl1 = ex2f(mrun1 - mn1);
        mrun0 = mn0; mrun1 = mn1;
        lsum0 *= scl0; lsum1 *= scl1;
        #pragma unroll
        for (int nt = 0; nt < 4; nt++) {
            O[nt][0] *= scl0; O[nt][1] *= scl0;
            O[nt][2] *= scl1; O[nt][3] *= scl1;
        }
        #pragma unroll
        for (int nt = 0; nt < 8; nt++) {
            sc[nt][0] = ex2f(sc[nt][0] - mn0);
            sc[nt][1] = ex2f(sc[nt][1] - mn0);
            sc[nt][2] = ex2f(sc[nt][2] - mn1);
            sc[nt][3] = ex2f(sc[nt][3] - mn1);
            lsum0 += sc[nt][0] + sc[nt][1];
            lsum1 += sc[nt][2] + sc[nt][3];
        }

        #pragma unroll
        for (int ks = 0; ks < 4; ks++) {
            uint32_t a0 = pack_h2(sc[2*ks][0],   sc[2*ks][1]);
            uint32_t a1 = pack_h2(sc[2*ks][2],   sc[2*ks][3]);
            uint32_t a2 = pack_h2(sc[2*ks+1][0], sc[2*ks+1][1]);
            uint32_t a3 = pack_h2(sc[2*ks+1][2], sc[2*ks+1][3]);
            #pragma unroll
            for (int j = 0; j < 2; j++) {
                uint32_t b0, b1, b2, b3;
                uint32_t addr = sv + (uint32_t)(j*16 + (lane & 7) + ((lane >> 4) & 1)*8)*144
                              + (uint32_t)(ks*32 + ((lane >> 3) & 1)*16);
                ldmatrix_x4(b0, b1, b2, b3, addr);
                mma16816(O[2*j],   a0, a1, a2, a3, b0, b1);
                mma16816(O[2*j+1], a0, a1, a2, a3, b2, b3);
            }
        }

        if (more) {
            *reinterpret_cast<uint4*>(s_k[1-cur] + krow*80 + ksub*16)  = pk;
            *reinterpret_cast<uint4*>(s_v[1-cur] + vrow*144 + vsub*16) = pv;
        }
        __syncthreads();
    }

    lsum0 += __shfl_xor_sync(0xffffffffu, lsum0, 1);
    lsum0 += __shfl_xor_sync(0xffffffffu, lsum0, 2);
    lsum1 += __shfl_xor_sync(0xffffffffu, lsum1, 1);
    lsum1 += __shfl_xor_sync(0xffffffffu, lsum1, 2);
    float inv0 = 1.f / lsum0, inv1 = 1.f / lsum1;

    const int row0 = q0 + m0 + (lane >> 2);
    const int cp = (lane & 3)*2;
    float* abase = g_a + (size_t)(n*CC + g*CG)*HW;
    #pragma unroll
    for (int nt = 0; nt < 4; nt++) {
        int ch = nt*8 + cp;
        abase[(size_t)ch*HW + row0]           = O[nt][0]*inv0;
        abase[(size_t)(ch+1)*HW + row0]       = O[nt][1]*inv0;
        abase[(size_t)ch*HW + row0 + 8]       = O[nt][2]*inv1;
        abase[(size_t)(ch+1)*HW + row0 + 8]   = O[nt][3]*inv1;
    }
}

// ---------------------------------------------------------------------------
// Kernel 4: LSTM epilogue — tanh.approx.f32 activations (1 MUFU each)
// ---------------------------------------------------------------------------
__global__ __launch_bounds__(256) void lstm_kernel(
    const float* __restrict__ Wa0, const float* __restrict__ Wa1,
    const float* __restrict__ Wa2, const float* __restrict__ Wa3,
    const float* __restrict__ b0,  const float* __restrict__ b1,
    const float* __restrict__ b2,  const float* __restrict__ b3,
    const float* __restrict__ c_prev, float* __restrict__ out)
{
    __shared__ float s_a[CC][8];
    const int n  = blockIdx.y;
    const int p0 = blockIdx.x * 8;
    const int t  = threadIdx.x;

    for (int i = t; i < CC*8; i += 256) {
        int ch = i >> 3, p = i & 7;
        s_a[ch][p] = g_a[((size_t)(n*CC + ch))*HW + p0 + p];
    }
    __syncthreads();

    const int c = t, g = c >> 5;
    float a0[8], a1[8], a2[8], a3[8];
    #pragma unroll
    for (int p = 0; p < 8; p++) { a0[p] = a1[p] = a2[p] = a3[p] = 0.f; }

    const float* wa0 = Wa0 + c*CG;
    const float* wa1 = Wa1 + c*CG;
    const float* wa2 = Wa2 + c*CG;
    const float* wa3 = Wa3 + c*CG;
    for (int cg = 0; cg < CG; cg++) {
        float w0 = wa0[cg], w1 = wa1[cg], w2 = wa2[cg], w3 = wa3[cg];
        const float* ar = s_a[g*CG + cg];
        #pragma unroll
        for (int p = 0; p < 8; p++) {
            float av = ar[p];
            a0[p] = fmaf(w0, av, a0[p]);
            a1[p] = fmaf(w1, av, a1[p]);
            a2[p] = fmaf(w2, av, a2[p]);
            a3[p] = fmaf(w3, av, a3[p]);
        }
    }

    const float bi = b0[c], bf = b1[c], bg = b2[c], bo = b3[c];
    const int idx0 = (n*CC + c)*HW + p0;
    #pragma unroll
    for (int p = 0; p < 8; p++) {
        int idx = idx0 + p;
        float gi = sigfast(a0[p] + __half2float(g_gate16[                idx]) + bi);
        float gf = sigfast(a1[p] + __half2float(g_gate16[  STRIDE_GATE + idx]) + bf);
        float gg = tanhfast(a2[p] + __half2float(g_gate16[2*STRIDE_GATE + idx]) + bg);
        float go = sigfast(a3[p] + __half2float(g_gate16[3*STRIDE_GATE + idx]) + bo);
        float cn = gf * c_prev[idx] + gi * gg;
        out[idx] = go * tanhfast(cn);
    }
}

// ---------------------------------------------------------------------------
extern "C" void kernel_launch(void* const* d_in, const int* in_sizes, int n_in,
                              void* d_out, int out_size)
{
    const float* inp    = (const float*)d_in[0];
    const float* h_prev = (const float*)d_in[1];
    const float* c_prev = (const float*)d_in[2];
    const float* Wx     = (const float*)d_in[3];
    const float* Wxg    = (const float*)d_in[4];
    const float* tau    = (const float*)d_in[5];
    const float* Wq     = (const float*)d_in[6];
    const float* Wk     = (const float*)d_in[7];
    const float* Wv     = (const float*)d_in[8];
    const float* Wa_i   = (const float*)d_in[9];
    const float* Wxh_i  = (const float*)d_in[10];
    const float* b_i    = (const float*)d_in[11];
    const float* Wa_f   = (const float*)d_in[12];
    const float* Wxh_f  = (const float*)d_in[13];
    const float* b_f    = (const float*)d_in[14];
    const float* Wa_g   = (const float*)d_in[15];
    const float* Wxh_g  = (const float*)d_in[16];
    const float* b_g    = (const float*)d_in[17];
    const float* Wa_o   = (const float*)d_in[18];
    const float* Wxh_o  = (const float*)d_in[19];
    const float* b_o    = (const float*)d_in[20];
    float* out = (float*)d_out;

    cudaFuncSetAttribute(conv_all_mma,
                         cudaFuncAttributeMaxDynamicSharedMemorySize, SMT_CONV);
    cudaFuncSetAttribute(prep_wfrag,
                         cudaFuncAttributeMaxDynamicSharedMemorySize, PREP_SMEM);

    prep_wfrag      <<<224, 256, PREP_SMEM>>>(Wq, Wxh_i, Wxh_f, Wxh_g, Wxh_o, Wk, Wv);
    prep_pfrag      <<<80, 256>>>(Wx, Wxg);
    trans16         <<<dim3(HW/32, 10, NB), 256>>>(inp, h_prev);
    proj_mma        <<<dim3(72, 4), 256>>>();
    conv_all_mma    <<<dim3(8, 7, NB*GG), 256, SMT_CONV>>>(tau);
    attn_mma        <<<dim3(HW/128, NB*GG), 256>>>();
    lstm_kernel     <<<dim3(HW/8, NB), 256>>>(Wa_i, Wa_f, Wa_g, Wa_o,
                                              b_i, b_f, b_g, b_o, c_prev, out);
}